// round 8
// baseline (speedup 1.0000x reference)
#include <cuda_runtime.h>
#include <cstdint>

#define FULLM 0xffffffffu

namespace {
constexpr int T_STEPS = 128;
constexpr int NCH = 17;
constexpr int IMG_FLOATS = T_STEPS * NCH;       // 2176
constexpr int IMG_F4 = IMG_FLOATS / 4;          // 544
constexpr int IMG_BYTES = IMG_FLOATS * 4;       // 8704
}

// ---- JAX Brent-Kung 128-scan, bit-identical bracketing (verified R4-R7).
// Upsweep leaves on every lane l the balanced sum of the aligned block
// ending at l (size = lowest set bit of l+1). The inclusive prefix at l is
// the fold-left of the aligned blocks in the binary decomposition of l+1,
// seeded by the cross-warp prefix E_w; lane 31 takes the balanced Sw. ----

__device__ __forceinline__ float scan_up1(float r, int lane) {
#pragma unroll
    for (int h = 1; h <= 16; h <<= 1) {
        float u = __shfl_up_sync(FULLM, r, h);
        if ((lane & (2 * h - 1)) == (2 * h - 1)) r = __fadd_rn(u, r);
    }
    return r;
}

__device__ __forceinline__ void scan_up2(float& a, float& b, int lane) {
#pragma unroll
    for (int h = 1; h <= 16; h <<= 1) {
        float ua = __shfl_up_sync(FULLM, a, h);
        float ub = __shfl_up_sync(FULLM, b, h);
        if ((lane & (2 * h - 1)) == (2 * h - 1)) {
            a = __fadd_rn(ua, a);
            b = __fadd_rn(ub, b);
        }
    }
}

// Cross-warp fold-left seed E_w and full-prefix Sw from warp totals T[4].
// Brackets identical to R5/R7 downsweep version.
__device__ __forceinline__ void scan_tops(const float* __restrict__ T, int w,
                                          float& E, float& Sw) {
    const float s1 = __fadd_rn(T[0], T[1]);
    const float S2 = __fadd_rn(s1, T[2]);
    const float S3 = __fadd_rn(s1, __fadd_rn(T[2], T[3]));
    E  = (w == 1) ? T[0] : (w == 2) ? s1 : S2;
    Sw = (w == 0) ? T[0] : (w == 1) ? s1 : (w == 2) ? S2 : S3;
}

struct BkIdx {
    int p0, p1, p2, p3, p4;
    bool h1, h2, h3, h4;
};

__device__ __forceinline__ BkIdx bk_indices(int lane) {
    BkIdx o;
    int rem = lane + 1;   // 1..32
    int pref;
    {   // m=0: always present
        int b = 31 - __clz(rem);
        pref = 1 << b; rem -= 1 << b; o.p0 = pref - 1;
    }
    o.h1 = rem != 0;
    {   int b = 31 - __clz(rem | 1); int a = o.h1 ? (1 << b) : 0;
        pref += a; rem -= a; o.p1 = o.h1 ? pref - 1 : 0; }
    o.h2 = rem != 0;
    {   int b = 31 - __clz(rem | 1); int a = o.h2 ? (1 << b) : 0;
        pref += a; rem -= a; o.p2 = o.h2 ? pref - 1 : 0; }
    o.h3 = rem != 0;
    {   int b = 31 - __clz(rem | 1); int a = o.h3 ? (1 << b) : 0;
        pref += a; rem -= a; o.p3 = o.h3 ? pref - 1 : 0; }
    o.h4 = rem != 0;
    {   int b = 31 - __clz(rem | 1); int a = o.h4 ? (1 << b) : 0;
        pref += a; rem -= a; o.p4 = o.h4 ? pref - 1 : 0; }
    return o;
}

__device__ __forceinline__ float scan_fin1(float u, int lane, int w,
                                           float E, float Sw, const BkIdx& q) {
    const float g0 = __shfl_sync(FULLM, u, q.p0);
    const float g1 = __shfl_sync(FULLM, u, q.p1);
    const float g2 = __shfl_sync(FULLM, u, q.p2);
    const float g3 = __shfl_sync(FULLM, u, q.p3);
    const float g4 = __shfl_sync(FULLM, u, q.p4);
    float v = (w > 0) ? __fadd_rn(E, g0) : g0;
    if (q.h1) v = __fadd_rn(v, g1);
    if (q.h2) v = __fadd_rn(v, g2);
    if (q.h3) v = __fadd_rn(v, g3);
    if (q.h4) v = __fadd_rn(v, g4);
    if (lane == 31) v = Sw;
    return v;
}

__device__ __forceinline__ void scan_fin2(float ua, float ub, int lane, int w,
                                          float Ea, float Swa, float Eb, float Swb,
                                          const BkIdx& q, float& va, float& vb) {
    const float a0 = __shfl_sync(FULLM, ua, q.p0);
    const float b0 = __shfl_sync(FULLM, ub, q.p0);
    const float a1 = __shfl_sync(FULLM, ua, q.p1);
    const float b1 = __shfl_sync(FULLM, ub, q.p1);
    const float a2 = __shfl_sync(FULLM, ua, q.p2);
    const float b2 = __shfl_sync(FULLM, ub, q.p2);
    const float a3 = __shfl_sync(FULLM, ua, q.p3);
    const float b3 = __shfl_sync(FULLM, ub, q.p3);
    const float a4 = __shfl_sync(FULLM, ua, q.p4);
    const float b4 = __shfl_sync(FULLM, ub, q.p4);
    va = (w > 0) ? __fadd_rn(Ea, a0) : a0;
    vb = (w > 0) ? __fadd_rn(Eb, b0) : b0;
    if (q.h1) { va = __fadd_rn(va, a1); vb = __fadd_rn(vb, b1); }
    if (q.h2) { va = __fadd_rn(va, a2); vb = __fadd_rn(vb, b2); }
    if (q.h3) { va = __fadd_rn(va, a3); vb = __fadd_rn(vb, b3); }
    if (q.h4) { va = __fadd_rn(va, a4); vb = __fadd_rn(vb, b4); }
    if (lane == 31) { va = Swa; vb = Swb; }
}

__device__ __forceinline__ void cp_async16(float4* dst_smem, const float4* src_gmem) {
    uint32_t s = (uint32_t)__cvta_generic_to_shared(dst_smem);
    asm volatile("cp.async.cg.shared.global [%0], [%1], 16;" ::
                 "r"(s), "l"(src_gmem));
}

__global__ __launch_bounds__(128, 14)
void car_dyn_kernel(const float* __restrict__ state,
                    const float* __restrict__ pact,
                    const float* __restrict__ Hmap,
                    const float* __restrict__ Nrm,
                    float* __restrict__ out_states,
                    float* __restrict__ out_pa)
{
    __shared__ __align__(16) float img[IMG_FLOATS];   // 8704 B working image
    __shared__ float tot[5][4];
    __shared__ float bnd[4][2];

    const int tid  = threadIdx.x;
    const int lane = tid & 31;
    const int w    = tid >> 5;
    const int k    = blockIdx.x;

    float4* img4 = reinterpret_cast<float4*>(img);
    const float4* src4 = reinterpret_cast<const float4*>(state) + (size_t)k * IMG_F4;
#pragma unroll
    for (int i = 0; i < 4; ++i) cp_async16(&img4[tid + 128 * i], &src4[tid + 128 * i]);
    if (tid < 32) cp_async16(&img4[512 + tid], &src4[512 + tid]);
    asm volatile("cp.async.commit_group;" ::: "memory");

    const float2 pa = reinterpret_cast<const float2*>(pact)[(size_t)k * T_STEPS + tid];
    const BkIdx q = bk_indices(lane);

    // ---- scans 1&2: cumsum(pa * DT) (overlap with in-copy) ----
    float u0 = __fmul_rn(pa.x, 0.02f);
    float u1 = __fmul_rn(pa.y, 0.02f);
    scan_up2(u0, u1, lane);
    if (lane == 31) { tot[0][w] = u0; tot[1][w] = u1; }

    asm volatile("cp.async.wait_group 0;" ::: "memory");
    __syncthreads();   // (1) image + warp totals ready

    float r0, r1;
    {
        float E0, S0, E1, S1;
        scan_tops(tot[0], w, E0, S0);
        scan_tops(tot[1], w, E1, S1);
        scan_fin2(u0, u1, lane, w, E0, S0, E1, S1, q, r0, r1);
    }

    float* rec = img + tid * NCH;   // base 17*tid -> conflict-free scalars

    // ---- controls ----
    const float s15 = rec[15], s16 = rec[16];
    float c0 = fminf(fmaxf(__fadd_rn(s15, __fmul_rn(4.0f, r0)), -1.f), 1.f);
    float c1 = fminf(fmaxf(__fadd_rn(s16, __fmul_rn(4.0f, r1)), -1.f), 1.f);
    c1 = fminf(fmaxf(c1, 0.f), 0.5f);
    const float cm0 = __fsub_rn(c0, s15);
    const float cm1 = __fsub_rn(c1, s16);
    rec[15] = c0; rec[16] = c1;
    rec[7] = 0.f; rec[8] = 0.f;      // vy, vz (ch9 = ax passes through)

    // ---- dynamics elementwise ----
    const float Kc = __fmul_rn(tanf(c0), 2.0f);       // /0.5 exact
    const float vx = __fmul_rn(c1, 17.0f);
    const float dS = __fmul_rn(vx, 0.02f);
    const float w1 = __fmul_rn(vx, Kc);
    const float a0 = fminf(fmaxf(__fmul_rn(vx, w1), -14.f), 14.f);
    const float wz = __fdiv_rn(a0, fmaxf(vx, 1.f));   // vx<=8.5 so min(,25) never binds
    rec[6] = vx; rec[14] = wz;

    // ---- scan 3 upsweep (wz) + cm boundary exchange, one sync ----
    float u2 = scan_up1(wz, lane);
    if (lane == 31) { tot[2][w] = u2; bnd[w][0] = cm0; bnd[w][1] = cm1; }
    __syncthreads();   // (2)

    // ---- new_pa straight to global ----
    {
        float pm0 = __shfl_up_sync(FULLM, cm0, 1);
        float pm1 = __shfl_up_sync(FULLM, cm1, 1);
        if (lane == 0 && w > 0) { pm0 = bnd[w - 1][0]; pm1 = bnd[w - 1][1]; }
        float np0 = __fdiv_rn(__fsub_rn(cm0, pm0), 0.08f);
        float np1 = __fdiv_rn(__fsub_rn(cm1, pm1), 0.08f);
        if (tid == 0) { np0 = pa.x; np1 = pa.y; }
        reinterpret_cast<float2*>(out_pa)[(size_t)k * T_STEPS + tid] =
            make_float2(np0, np1);
    }

    float r2;
    {
        float E2, S2;
        scan_tops(tot[2], w, E2, S2);
        r2 = scan_fin1(u2, lane, w, E2, S2, q);
    }
    const float yaw = __fadd_rn(rec[5], __fmul_rn(0.02f, r2));
    rec[5] = yaw;
    float sy, cy;
    sincosf(yaw, &sy, &cy);

    // ---- scans 4&5: x, y ----
    float u3 = __fmul_rn(dS, cy);
    float u4 = __fmul_rn(dS, sy);
    scan_up2(u3, u4, lane);
    if (lane == 31) { tot[3][w] = u3; tot[4][w] = u4; }
    __syncthreads();   // (3)
    float r3, r4;
    {
        float E3, S3, E4, S4;
        scan_tops(tot[3], w, E3, S3);
        scan_tops(tot[4], w, E4, S4);
        scan_fin2(u3, u4, lane, w, E3, S3, E4, S4, q, r3, r4);
    }
    const float x = __fadd_rn(rec[0], r3);
    const float y = __fadd_rn(rec[1], r4);
    rec[0] = x; rec[1] = y;

    // ---- BEV gather ----
    int iX = (int)(__fmul_rn(__fadd_rn(x, 32.f), 4.f));
    int iY = (int)(__fmul_rn(__fadd_rn(y, 32.f), 4.f));
    iX = min(max(iX, 0), 255);
    iY = min(max(iY, 0), 255);
    const int g = iY * 256 + iX;
    const float z  = __ldg(Hmap + g);
    const float nx = __ldg(Nrm + 3 * g + 0);
    const float ny = __ldg(Nrm + 3 * g + 1);
    const float nz = __ldg(Nrm + 3 * g + 2);

    const float lz = __fsub_rn(__fmul_rn(nx, sy), __fmul_rn(ny, cy));
    const float lx = __fsub_rn(0.f, __fmul_rn(nz, sy));
    const float ly = __fmul_rn(nz, cy);
    const float roll = asinf(lz);
    const float fz = __fsub_rn(__fmul_rn(lx, ny), __fmul_rn(ly, nx));
    const float pitch = -asinf(fz);
    rec[2] = z; rec[3] = roll; rec[4] = pitch;

    // ---- roll/pitch boundary exchange + diffs ----
    if (lane == 31) { bnd[w][0] = roll; bnd[w][1] = pitch; }
    __syncthreads();   // (4)
    float pr = __shfl_up_sync(FULLM, roll, 1);
    float pp = __shfl_up_sync(FULLM, pitch, 1);
    if (lane == 0 && w > 0) { pr = bnd[w - 1][0]; pp = bnd[w - 1][1]; }
    float wxv = __fdiv_rn(__fsub_rn(roll, pr), 0.02f);
    float wyv = __fdiv_rn(__fsub_rn(pitch, pp), 0.02f);
    if (tid == 0) { wxv = rec[12]; wyv = rec[13]; }   // input ch12/13 intact
    const float ay = __fadd_rn(__fmul_rn(vx, wz), __fmul_rn(9.8f, lz));
    const float az = __fadd_rn(__fmul_rn(__fsub_rn(0.f, vx), wyv),
                               __fmul_rn(9.8f, nz));
    rec[10] = ay; rec[11] = az; rec[12] = wxv; rec[13] = wyv;

    __syncthreads();   // (5) image final

    // ---- single bulk DMA: smem -> global ----
    if (tid == 0) {
        float* dst = out_states + (size_t)k * IMG_FLOATS;
        const uint32_t img_s = (uint32_t)__cvta_generic_to_shared(img);
        asm volatile("fence.proxy.async.shared::cta;" ::: "memory");
        asm volatile(
            "cp.async.bulk.global.shared::cta.bulk_group [%0], [%1], %2;"
            :: "l"(dst), "r"(img_s), "r"((uint32_t)IMG_BYTES) : "memory");
        asm volatile("cp.async.bulk.commit_group;" ::: "memory");
        asm volatile("cp.async.bulk.wait_group.read 0;" ::: "memory");
    }
}

extern "C" void kernel_launch(void* const* d_in, const int* in_sizes, int n_in,
                              void* d_out, int out_size)
{
    const float* state = (const float*)d_in[0];
    const float* pact  = (const float*)d_in[1];
    const float* Hmap  = (const float*)d_in[2];
    const float* Nrm   = (const float*)d_in[3];

    const int K = (in_sizes[1] / 2) / T_STEPS;
    float* out_states = (float*)d_out;
    float* out_pa     = (float*)d_out + (size_t)in_sizes[0];

    car_dyn_kernel<<<K, 128>>>(state, pact, Hmap, Nrm, out_states, out_pa);
}